// round 6
// baseline (speedup 1.0000x reference)
#include <cuda_runtime.h>
#include <math_constants.h>

// Heatmaps_57363583205469: 3x3 max-pool peak mask + sigmoid gating.
//   keep = (maxpool3x3(h) == h) && (sigmoid(h) > 0.05)
//   out  = keep ? sigmoid(h) : 0
// Shapes: [16, 17, 512, 512] fp32 -> 272 planes of 512x512.
//
// R5: 8 columns per thread (2 independent float4 LDGs per row) to double
// per-warp MLP and halve shuffle/index overhead per element. 64-thread
// blocks, 64-row strips -> 2176 blocks, all resident in one wave.
// Rolling 3-row register window for the vertical max; no smem, no barriers.

#define W 512
#define H 512
#define ROWS_PER_BLOCK 64
// logit(0.05f) computed in double precision: -ln(1/0.05000000074505806 - 1)
#define XTHRESH (-2.9444389643f)

struct f8 { float4 a, b; };

__device__ __forceinline__ f8 row_hmax8(const float* __restrict__ row,
                                        int c0, int lane, f8& v)
{
    v.a = __ldg(reinterpret_cast<const float4*>(row + c0));
    v.b = __ldg(reinterpret_cast<const float4*>(row + c0 + 4));

    // chunk-edge neighbors from adjacent lanes (interior comes from registers)
    float l = __shfl_up_sync(0xffffffffu, v.b.w, 1);
    float r = __shfl_down_sync(0xffffffffu, v.a.x, 1);
    if (lane == 0)  l = (c0 == 0)     ? -CUDART_INF_F : __ldg(row + c0 - 1);
    if (lane == 31) r = (c0 + 8 >= W) ? -CUDART_INF_F : __ldg(row + c0 + 8);

    f8 h;
    h.a.x = fmaxf(fmaxf(l,     v.a.x), v.a.y);
    h.a.y = fmaxf(fmaxf(v.a.x, v.a.y), v.a.z);
    h.a.z = fmaxf(fmaxf(v.a.y, v.a.z), v.a.w);
    h.a.w = fmaxf(fmaxf(v.a.z, v.a.w), v.b.x);
    h.b.x = fmaxf(fmaxf(v.a.w, v.b.x), v.b.y);
    h.b.y = fmaxf(fmaxf(v.b.x, v.b.y), v.b.z);
    h.b.z = fmaxf(fmaxf(v.b.y, v.b.z), v.b.w);
    h.b.w = fmaxf(fmaxf(v.b.z, v.b.w), r);
    return h;
}

__device__ __forceinline__ float peak_val(float m, float v)
{
    // sigmoid via fast EX2 + RCP (2 MUFU) — rel err ~1e-6, hides under DRAM.
    float s = __fdividef(1.0f, 1.0f + __expf(-v));
    return (m == v && v > XTHRESH) ? s : 0.0f;
}

__global__ void __launch_bounds__(64)
Heatmaps_57363583205469_kernel(const float* __restrict__ in,
                               float* __restrict__ out)
{
    const int plane = blockIdx.y;                 // 0..271 (B*K planes)
    const int strip = blockIdx.x;                 // 0..7   (64-row strips)
    const int lane  = threadIdx.x & 31;
    const int c0    = threadIdx.x << 3;           // 8 cols per thread

    const float* __restrict__ base  = in  + (size_t)plane * (W * H);
    float*       __restrict__ obase = out + (size_t)plane * (W * H);
    const int r0 = strip * ROWS_PER_BLOCK;

    const float4 ninf4 = make_float4(-CUDART_INF_F, -CUDART_INF_F,
                                     -CUDART_INF_F, -CUDART_INF_F);
    f8 ninf; ninf.a = ninf4; ninf.b = ninf4;

    f8 v_curr, v_next, v_scratch;
    f8 h_prev, h_curr, h_next;

    h_prev = (r0 == 0) ? ninf
                       : row_hmax8(base + (size_t)(r0 - 1) * W, c0, lane, v_scratch);
    h_curr = row_hmax8(base + (size_t)r0 * W, c0, lane, v_curr);

    #pragma unroll 4
    for (int r = r0; r < r0 + ROWS_PER_BLOCK; ++r) {
        if (r + 1 < H) {
            h_next = row_hmax8(base + (size_t)(r + 1) * W, c0, lane, v_next);
        } else {
            h_next = ninf;
            v_next = ninf;
        }

        float4 oa, ob;
        oa.x = peak_val(fmaxf(fmaxf(h_prev.a.x, h_curr.a.x), h_next.a.x), v_curr.a.x);
        oa.y = peak_val(fmaxf(fmaxf(h_prev.a.y, h_curr.a.y), h_next.a.y), v_curr.a.y);
        oa.z = peak_val(fmaxf(fmaxf(h_prev.a.z, h_curr.a.z), h_next.a.z), v_curr.a.z);
        oa.w = peak_val(fmaxf(fmaxf(h_prev.a.w, h_curr.a.w), h_next.a.w), v_curr.a.w);
        ob.x = peak_val(fmaxf(fmaxf(h_prev.b.x, h_curr.b.x), h_next.b.x), v_curr.b.x);
        ob.y = peak_val(fmaxf(fmaxf(h_prev.b.y, h_curr.b.y), h_next.b.y), v_curr.b.y);
        ob.z = peak_val(fmaxf(fmaxf(h_prev.b.z, h_curr.b.z), h_next.b.z), v_curr.b.z);
        ob.w = peak_val(fmaxf(fmaxf(h_prev.b.w, h_curr.b.w), h_next.b.w), v_curr.b.w);

        float* orow = obase + (size_t)r * W + c0;
        *reinterpret_cast<float4*>(orow)     = oa;
        *reinterpret_cast<float4*>(orow + 4) = ob;

        h_prev = h_curr;
        h_curr = h_next;
        v_curr = v_next;
    }
}

extern "C" void kernel_launch(void* const* d_in, const int* in_sizes, int n_in,
                              void* d_out, int out_size)
{
    const float* in  = (const float*)d_in[0];
    float*       out = (float*)d_out;
    const int planes = in_sizes[0] / (W * H);     // 16 * 17 = 272

    dim3 grid(H / ROWS_PER_BLOCK, planes);
    Heatmaps_57363583205469_kernel<<<grid, 64>>>(in, out);
}